// round 8
// baseline (speedup 1.0000x reference)
#include <cuda_runtime.h>
#include <cuda_fp16.h>
#include <cstdint>

#define NN 100000
#define NE 1000000
#define D  128
#define R  16
#define TE 128   // edges per MMA tile
#define NB 9     // blocks per relation (grid = R*NB = 144)

// ---------------- device scratch (no allocation allowed) ----------------
__device__ float g_Z[(size_t)NN * D];
__device__ __half g_Xh[(size_t)NN * D];          // layer-1 input, fp16
__device__ __half g_Hh[(size_t)NN * D];          // layer-1 output, fp16
__device__ __half g_WT[2][R * D * D];            // [layer][r][n][k] = W[k][n], fp16
__device__ __half g_rootT[2][D * D];
__device__ int g_cnt[NN];
__device__ int g_sorted[NE];
__device__ int g_hist[R];
__device__ int g_base[R + 1];
__device__ int g_cursor[R];

// ---- smem maps (row pitch 272B = 256B data + 16B pad; conflict-free ldsm) ----
#define PITCH   272
#define WBLK    34816            // 128 rows * 272
// rgemm: W @0, A bufs @ WBLK + i*WBLK (triple buffered)
#define SA_BASE 34816
#define SMEM_RG 139264           // 4*34816
// combine: W @0, A @WBLK
#define SMEM_CB 69632

// ---------------- helpers ----------------
__device__ __forceinline__ uint32_t smem_u32(const void* p) {
    uint32_t a;
    asm("{ .reg .u64 t; cvta.to.shared.u64 t, %1; cvt.u32.u64 %0, t; }" : "=r"(a) : "l"(p));
    return a;
}
__device__ __forceinline__ void red_v2(float* p, float a, float b) {
    asm volatile("red.global.add.v2.f32 [%0], {%1,%2};" :: "l"(p), "f"(a), "f"(b) : "memory");
}
__device__ __forceinline__ void ldsm4(uint32_t addr, uint32_t& r0, uint32_t& r1,
                                      uint32_t& r2, uint32_t& r3) {
    asm volatile("ldmatrix.sync.aligned.m8n8.x4.shared.b16 {%0,%1,%2,%3}, [%4];"
                 : "=r"(r0), "=r"(r1), "=r"(r2), "=r"(r3) : "r"(addr));
}
__device__ __forceinline__ void mma16816(float* d, const uint32_t* a, uint32_t b0, uint32_t b1) {
    asm volatile(
        "mma.sync.aligned.m16n8k16.row.col.f32.f16.f16.f32 "
        "{%0,%1,%2,%3}, {%4,%5,%6,%7}, {%8,%9}, {%0,%1,%2,%3};"
        : "+f"(d[0]), "+f"(d[1]), "+f"(d[2]), "+f"(d[3])
        : "r"(a[0]), "r"(a[1]), "r"(a[2]), "r"(a[3]), "r"(b0), "r"(b1));
}
__device__ __forceinline__ void cp16(uint32_t saddr, const void* gaddr, int sz) {
    asm volatile("cp.async.cg.shared.global [%0], [%1], 16, %2;"
                 :: "r"(saddr), "l"(gaddr), "r"(sz) : "memory");
}
__device__ __forceinline__ void cp_commit() { asm volatile("cp.async.commit_group;" ::: "memory"); }

// single-term fp16 128x128x128 mainloop. W at wbase, A at abase.
// warp (mw,nw): rows mw*32..+31, cols nw*64..+63.
__device__ __forceinline__ void mma_main(uint32_t wbase, uint32_t abase,
                                         float acc[2][8][4], int mw, int nw, int lane) {
    const int rsel = ((lane >> 3) & 1) * 8 + (lane & 7);
    const int ksel = (lane >> 4) * 16;
#pragma unroll
    for (int kk = 0; kk < 8; kk++) {
        const int kb = kk * 32 + ksel;
        uint32_t aH[2][4];
#pragma unroll
        for (int a = 0; a < 2; a++) {
            uint32_t ro = (uint32_t)(mw * 32 + a * 16 + rsel) * PITCH + kb;
            ldsm4(abase + ro, aH[a][0], aH[a][1], aH[a][2], aH[a][3]);
        }
#pragma unroll
        for (int p = 0; p < 4; p++) {
            uint32_t wo = (uint32_t)(nw * 64 + p * 16 + rsel) * PITCH + kb;
            uint32_t bh[4];
            ldsm4(wbase + wo, bh[0], bh[1], bh[2], bh[3]);
#pragma unroll
            for (int a = 0; a < 2; a++) {
                mma16816(acc[a][2 * p],     aH[a], bh[0], bh[2]);
                mma16816(acc[a][2 * p + 1], aH[a], bh[1], bh[3]);
            }
        }
    }
}

// ---------------- setup kernels ----------------
__global__ void k_zero_meta() {
    int i = blockIdx.x * blockDim.x + threadIdx.x;
    if (i < R)  g_hist[i] = 0;
    if (i < NN) g_cnt[i] = 0;
}

__global__ void k_hist(const int* __restrict__ et, const int* __restrict__ dst) {
    __shared__ int sh[R];
    if (threadIdx.x < R) sh[threadIdx.x] = 0;
    __syncthreads();
    int e = blockIdx.x * blockDim.x + threadIdx.x;
    if (e < NE) {
        atomicAdd(&sh[et[e]], 1);
        atomicAdd(&g_cnt[dst[e]], 1);
    }
    __syncthreads();
    if (threadIdx.x < R && sh[threadIdx.x]) atomicAdd(&g_hist[threadIdx.x], sh[threadIdx.x]);
}

__global__ void k_scan() {
    int acc = 0;
    for (int r = 0; r < R; r++) {
        g_base[r] = acc;
        g_cursor[r] = acc;
        acc += g_hist[r];
    }
    g_base[R] = acc;
}

__global__ void k_sort(const int* __restrict__ et) {
    __shared__ int lh[R], lb[R];
    if (threadIdx.x < R) lh[threadIdx.x] = 0;
    __syncthreads();
    int e = blockIdx.x * blockDim.x + threadIdx.x;
    int t = -1, lp = 0;
    if (e < NE) {
        t = et[e];
        lp = atomicAdd(&lh[t], 1);
    }
    __syncthreads();
    if (threadIdx.x < R && lh[threadIdx.x] > 0)
        lb[threadIdx.x] = atomicAdd(&g_cursor[threadIdx.x], lh[threadIdx.x]);
    __syncthreads();
    if (t >= 0) g_sorted[lb[t] + lp] = e;
}

// transpose + fp16: W[k][n] -> WT[n][k]; bx 0..31 relations, 32..33 roots
__global__ void k_prepW(const float* __restrict__ W1, const float* __restrict__ W2,
                        const float* __restrict__ root1, const float* __restrict__ root2) {
    int bx = blockIdx.x;
    const float* W;
    __half* hi;
    if (bx < 32) {
        int layer = bx >> 4, r = bx & 15;
        W  = (layer ? W2 : W1) + (size_t)r * D * D;
        hi = g_WT[layer] + (size_t)r * D * D;
    } else {
        int layer = bx - 32;
        W  = layer ? root2 : root1;
        hi = g_rootT[layer];
    }
    for (int idx = threadIdx.x; idx < D * D; idx += blockDim.x) {
        int n = idx >> 7, k = idx & 127;
        hi[idx] = __float2half_rn(W[k * D + n]);
    }
}

__global__ void k_gather(const int* __restrict__ ent, const float* __restrict__ emb) {
    int id = blockIdx.x * blockDim.x + threadIdx.x;
    int n = id >> 5, t = id & 31;
    float4 v = ((const float4*)(emb + (size_t)ent[n] * D))[t];
    __half h[4] = {__float2half_rn(v.x), __float2half_rn(v.y),
                   __float2half_rn(v.z), __float2half_rn(v.w)};
    *(uint2*)(g_Xh + (size_t)n * D + t * 4) = *(uint2*)h;
}

__global__ void k_zeroZ() {
    size_t i = (size_t)blockIdx.x * blockDim.x + threadIdx.x;
    ((float4*)g_Z)[i] = make_float4(0.f, 0.f, 0.f, 0.f);
}

// ---------------- persistent edge GEMM + scatter ----------------
__device__ __forceinline__ void issue_A(const __half* __restrict__ Xh,
                                        const int* __restrict__ src,
                                        int ebase, int n, uint32_t abase, int tid) {
#pragma unroll
    for (int j = 0; j < 8; j++) {
        int id = tid + 256 * j;
        int row = id >> 4, c = id & 15;
        const void* g = Xh;
        int sz = 0;
        if (row < n) {
            int e = g_sorted[ebase + row];
            g = (const uint4*)(Xh + (size_t)src[e] * D) + c;
            sz = 16;
        }
        cp16(abase + (uint32_t)row * PITCH + (uint32_t)c * 16, g, sz);
    }
}

__global__ __launch_bounds__(256, 1)
void k_rgemm_mma(int layer, const int* __restrict__ src, const int* __restrict__ dst) {
    extern __shared__ unsigned char sm[];
    uint32_t sbase = smem_u32(sm);
    int tid = threadIdx.x, w = tid >> 5, lane = tid & 31;
    const int mw = w >> 1, nw = w & 1;

    int r = blockIdx.x / NB;
    int j = blockIdx.x % NB;
    int hist = g_hist[r];
    int sb   = g_base[r];
    int Tr   = (hist + TE - 1) / TE;
    int per  = (Tr + NB - 1) / NB;
    int tb   = j * per;
    int te   = tb + per;
    if (te > Tr) te = Tr;
    int nt = te - tb;
    if (nt <= 0) return;

    // stage W_r once
    const uint4* Wg = (const uint4*)(g_WT[layer] + (size_t)r * D * D);
#pragma unroll
    for (int q = 0; q < 8; q++) {
        int id = tid + 256 * q;
        uint32_t off = (uint32_t)(id >> 4) * PITCH + (uint32_t)(id & 15) * 16;
        *(uint4*)(sm + off) = Wg[id];
    }

    const __half* Xh = layer ? g_Hh : g_Xh;

    // prologue: prefetch tiles tb, tb+1 into bufs 0,1
    {
        int n0 = hist - tb * TE; if (n0 > TE) n0 = TE;
        issue_A(Xh, src, sb + tb * TE, n0, sbase + SA_BASE, tid);
        cp_commit();
        if (nt > 1) {
            int n1 = hist - (tb + 1) * TE; if (n1 > TE) n1 = TE;
            issue_A(Xh, src, sb + (tb + 1) * TE, n1, sbase + SA_BASE + WBLK, tid);
        }
        cp_commit();
    }

    const int g = lane >> 2, tig = lane & 3;
    int buf = 0;

    for (int ti = 0; ti < nt; ti++) {
        int t = tb + ti;
        int ebase = sb + t * TE;
        int n = hist - t * TE; if (n > TE) n = TE;
        uint32_t abase = sbase + SA_BASE + (uint32_t)buf * WBLK;

        asm volatile("cp.async.wait_group 1;" ::: "memory");
        __syncthreads();   // tile ti ready everywhere; all warps past mma of ti-1

        // refill buffer consumed at ti-1 with tile ti+2
        if (ti + 2 < nt) {
            int t2 = tb + ti + 2;
            int n2 = hist - t2 * TE; if (n2 > TE) n2 = TE;
            int b2 = buf + 2; if (b2 >= 3) b2 -= 3;
            issue_A(Xh, src, sb + t2 * TE, n2, sbase + SA_BASE + (uint32_t)b2 * WBLK, tid);
        }
        cp_commit();

        float acc[2][8][4];
#pragma unroll
        for (int a = 0; a < 2; a++)
#pragma unroll
            for (int q = 0; q < 8; q++)
#pragma unroll
                for (int z = 0; z < 4; z++) acc[a][q][z] = 0.f;

        mma_main(sbase, abase, acc, mw, nw, lane);

        // scatter straight from registers
#pragma unroll
        for (int a = 0; a < 2; a++) {
#pragma unroll
            for (int h = 0; h < 2; h++) {
                int row = mw * 32 + a * 16 + g + h * 8;
                if (row < n) {
                    int e = g_sorted[ebase + row];
                    float* p = g_Z + (size_t)dst[e] * D + nw * 64 + 2 * tig;
#pragma unroll
                    for (int q = 0; q < 8; q++)
                        red_v2(p + q * 8, acc[a][q][2 * h], acc[a][q][2 * h + 1]);
                }
            }
        }

        buf++; if (buf == 3) buf = 0;
    }
}

// ---------------- combine: out = Z/max(cnt,1) + X @ root (+ReLU, +fp16 store) ----------------
__global__ __launch_bounds__(256, 1)
void k_combine_mma(int layer, float* __restrict__ outp, int use_out) {
    extern __shared__ unsigned char sm[];
    uint32_t sbase = smem_u32(sm);
    int tid = threadIdx.x, w = tid >> 5, lane = tid & 31;
    const int mw = w >> 1, nw = w & 1;
    int t0 = blockIdx.x * TE;

    const uint4* Wg = (const uint4*)g_rootT[layer];
#pragma unroll
    for (int q = 0; q < 8; q++) {
        int id = tid + 256 * q;
        uint32_t off = (uint32_t)(id >> 4) * PITCH + (uint32_t)(id & 15) * 16;
        *(uint4*)(sm + off) = Wg[id];
    }
    const __half* Xh = layer ? g_Hh : g_Xh;
#pragma unroll
    for (int q = 0; q < 8; q++) {
        int id = tid + 256 * q;
        int row = id >> 4, c = id & 15;
        int grow = t0 + row;
        uint4 v = make_uint4(0, 0, 0, 0);
        if (grow < NN) v = ((const uint4*)(Xh + (size_t)grow * D))[c];
        *(uint4*)(sm + WBLK + (uint32_t)row * PITCH + (uint32_t)c * 16) = v;
    }
    __syncthreads();

    float acc[2][8][4];
#pragma unroll
    for (int a = 0; a < 2; a++)
#pragma unroll
        for (int q = 0; q < 8; q++)
#pragma unroll
            for (int z = 0; z < 4; z++) acc[a][q][z] = 0.f;

    mma_main(sbase, sbase + WBLK, acc, mw, nw, lane);

    const int g = lane >> 2, tig = lane & 3;
#pragma unroll
    for (int a = 0; a < 2; a++) {
#pragma unroll
        for (int h = 0; h < 2; h++) {
            int grow = t0 + mw * 32 + a * 16 + g + h * 8;
            if (grow < NN) {
                int cc = g_cnt[grow];
                float ic = 1.0f / (float)(cc > 1 ? cc : 1);
#pragma unroll
                for (int q = 0; q < 8; q++) {
                    int col = nw * 64 + q * 8 + 2 * tig;
                    float2 z = *(const float2*)(g_Z + (size_t)grow * D + col);
                    float o0 = acc[a][q][2 * h]     + z.x * ic;
                    float o1 = acc[a][q][2 * h + 1] + z.y * ic;
                    if (use_out) {
                        *(float2*)(outp + (size_t)grow * D + col) = make_float2(o0, o1);
                    } else {
                        o0 = o0 > 0.f ? o0 : 0.f;
                        o1 = o1 > 0.f ? o1 : 0.f;
                        __half hh[2] = {__float2half_rn(o0), __float2half_rn(o1)};
                        *(uint32_t*)(g_Hh + (size_t)grow * D + col) = *(uint32_t*)hh;
                    }
                }
            }
        }
    }
}

// ---------------- host ----------------
extern "C" void kernel_launch(void* const* d_in, const int* in_sizes, int n_in,
                              void* d_out, int out_size) {
    const int*   entity = (const int*)d_in[0];
    const int*   eidx   = (const int*)d_in[1];
    const int*   etype  = (const int*)d_in[2];
    const float* emb    = (const float*)d_in[4];
    const float* W1     = (const float*)d_in[5];
    const float* root1  = (const float*)d_in[6];
    const float* W2     = (const float*)d_in[7];
    const float* root2  = (const float*)d_in[8];
    const int* src = eidx;
    const int* dst = eidx + NE;
    float* out = (float*)d_out;

    static int attr_done = 0;
    if (!attr_done) {
        cudaFuncSetAttribute(k_rgemm_mma,   cudaFuncAttributeMaxDynamicSharedMemorySize, SMEM_RG);
        cudaFuncSetAttribute(k_combine_mma, cudaFuncAttributeMaxDynamicSharedMemorySize, SMEM_CB);
        attr_done = 1;
    }

    int gE = (NE + 255) / 256;
    int gN = (NN + 255) / 256;
    int gZ = (NN * D / 4) / 256;
    int gC = (NN + TE - 1) / TE;

    k_zero_meta<<<gN, 256>>>();
    k_hist<<<gE, 256>>>(etype, dst);
    k_scan<<<1, 1>>>();
    k_sort<<<gE, 256>>>(etype);
    k_prepW<<<34, 256>>>(W1, W2, root1, root2);
    k_gather<<<NN / 8, 256>>>(entity, emb);

    // Layer 1
    k_zeroZ<<<gZ, 256>>>();
    k_rgemm_mma<<<R * NB, 256, SMEM_RG>>>(0, src, dst);
    k_combine_mma<<<gC, 256, SMEM_CB>>>(0, out, 0);

    // Layer 2
    k_zeroZ<<<gZ, 256>>>();
    k_rgemm_mma<<<R * NB, 256, SMEM_RG>>>(1, src, dst);
    k_combine_mma<<<gC, 256, SMEM_CB>>>(1, out, 1);
}

// round 9
// speedup vs baseline: 1.3897x; 1.3897x over previous
#include <cuda_runtime.h>
#include <cuda_fp16.h>
#include <cstdint>

#define NN 100000
#define NE 1000000
#define D  128
#define R  16
#define TE 256   // edges per MMA tile
#define NB 9     // blocks per relation (grid = R*NB = 144)

// ---------------- device scratch (no allocation allowed) ----------------
__device__ float g_Z[(size_t)NN * D];
__device__ __half g_Xh[(size_t)NN * D];          // layer-1 input, fp16
__device__ __half g_Hh[(size_t)NN * D];          // layer-1 output, fp16
__device__ __half g_WT[2][R * D * D];            // [layer][r][n][k] = W[k][n], fp16
__device__ __half g_rootT[2][D * D];
__device__ int g_cnt[NN];
__device__ int g_sorted[NE];
__device__ int g_hist[R];
__device__ int g_base[R + 1];
__device__ int g_cursor[R];

// ---- smem maps: pitch 256B, XOR chunk swizzle (conflict-free ldsm) ----
// rgemm: W(128 rows) @0 = 32KB; A bufs (256 rows = 64KB) triple buffered
#define WSZ     32768
#define ABLK    65536
#define SA_BASE 32768
#define SMEM_RG 229376           // 32768 + 3*65536
// combine: W @0 (32KB), A(128 rows) @32768 (32KB)
#define SMEM_CB 65536

// chunk swizzle: logical 16B chunk c (0..15) of row -> physical chunk
__device__ __forceinline__ uint32_t swz(int row, int c) {
    return (uint32_t)(((c & 7) ^ (row & 7)) | (c & 8));
}

// ---------------- helpers ----------------
__device__ __forceinline__ uint32_t smem_u32(const void* p) {
    uint32_t a;
    asm("{ .reg .u64 t; cvta.to.shared.u64 t, %1; cvt.u32.u64 %0, t; }" : "=r"(a) : "l"(p));
    return a;
}
__device__ __forceinline__ void red_v2(float* p, float a, float b) {
    asm volatile("red.global.add.v2.f32 [%0], {%1,%2};" :: "l"(p), "f"(a), "f"(b) : "memory");
}
__device__ __forceinline__ void ldsm4(uint32_t addr, uint32_t& r0, uint32_t& r1,
                                      uint32_t& r2, uint32_t& r3) {
    asm volatile("ldmatrix.sync.aligned.m8n8.x4.shared.b16 {%0,%1,%2,%3}, [%4];"
                 : "=r"(r0), "=r"(r1), "=r"(r2), "=r"(r3) : "r"(addr));
}
__device__ __forceinline__ void mma16816(float* d, const uint32_t* a, uint32_t b0, uint32_t b1) {
    asm volatile(
        "mma.sync.aligned.m16n8k16.row.col.f32.f16.f16.f32 "
        "{%0,%1,%2,%3}, {%4,%5,%6,%7}, {%8,%9}, {%0,%1,%2,%3};"
        : "+f"(d[0]), "+f"(d[1]), "+f"(d[2]), "+f"(d[3])
        : "r"(a[0]), "r"(a[1]), "r"(a[2]), "r"(a[3]), "r"(b0), "r"(b1));
}
__device__ __forceinline__ void cp16(uint32_t saddr, const void* gaddr, int sz) {
    asm volatile("cp.async.cg.shared.global [%0], [%1], 16, %2;"
                 :: "r"(saddr), "l"(gaddr), "r"(sz) : "memory");
}
__device__ __forceinline__ void cp_commit() { asm volatile("cp.async.commit_group;" ::: "memory"); }

// ---------------- setup kernels ----------------
__global__ void k_zero_meta() {
    int i = blockIdx.x * blockDim.x + threadIdx.x;
    if (i < R)  g_hist[i] = 0;
    if (i < NN) g_cnt[i] = 0;
}

__global__ void k_hist(const int* __restrict__ et, const int* __restrict__ dst) {
    __shared__ int sh[R];
    if (threadIdx.x < R) sh[threadIdx.x] = 0;
    __syncthreads();
    int e = blockIdx.x * blockDim.x + threadIdx.x;
    if (e < NE) {
        atomicAdd(&sh[et[e]], 1);
        atomicAdd(&g_cnt[dst[e]], 1);
    }
    __syncthreads();
    if (threadIdx.x < R && sh[threadIdx.x]) atomicAdd(&g_hist[threadIdx.x], sh[threadIdx.x]);
}

__global__ void k_scan() {
    int acc = 0;
    for (int r = 0; r < R; r++) {
        g_base[r] = acc;
        g_cursor[r] = acc;
        acc += g_hist[r];
    }
    g_base[R] = acc;
}

__global__ void k_sort(const int* __restrict__ et) {
    __shared__ int lh[R], lb[R];
    if (threadIdx.x < R) lh[threadIdx.x] = 0;
    __syncthreads();
    int e = blockIdx.x * blockDim.x + threadIdx.x;
    int t = -1, lp = 0;
    if (e < NE) {
        t = et[e];
        lp = atomicAdd(&lh[t], 1);
    }
    __syncthreads();
    if (threadIdx.x < R && lh[threadIdx.x] > 0)
        lb[threadIdx.x] = atomicAdd(&g_cursor[threadIdx.x], lh[threadIdx.x]);
    __syncthreads();
    if (t >= 0) g_sorted[lb[t] + lp] = e;
}

// transpose + fp16: W[k][n] -> WT[n][k]; bx 0..31 relations, 32..33 roots
__global__ void k_prepW(const float* __restrict__ W1, const float* __restrict__ W2,
                        const float* __restrict__ root1, const float* __restrict__ root2) {
    int bx = blockIdx.x;
    const float* W;
    __half* hi;
    if (bx < 32) {
        int layer = bx >> 4, r = bx & 15;
        W  = (layer ? W2 : W1) + (size_t)r * D * D;
        hi = g_WT[layer] + (size_t)r * D * D;
    } else {
        int layer = bx - 32;
        W  = layer ? root2 : root1;
        hi = g_rootT[layer];
    }
    for (int idx = threadIdx.x; idx < D * D; idx += blockDim.x) {
        int n = idx >> 7, k = idx & 127;
        hi[idx] = __float2half_rn(W[k * D + n]);
    }
}

__global__ void k_gather(const int* __restrict__ ent, const float* __restrict__ emb) {
    int id = blockIdx.x * blockDim.x + threadIdx.x;
    int n = id >> 5, t = id & 31;
    float4 v = ((const float4*)(emb + (size_t)ent[n] * D))[t];
    __half h[4] = {__float2half_rn(v.x), __float2half_rn(v.y),
                   __float2half_rn(v.z), __float2half_rn(v.w)};
    *(uint2*)(g_Xh + (size_t)n * D + t * 4) = *(uint2*)h;
}

__global__ void k_zeroZ() {
    size_t i = (size_t)blockIdx.x * blockDim.x + threadIdx.x;
    ((float4*)g_Z)[i] = make_float4(0.f, 0.f, 0.f, 0.f);
}

// ---------------- persistent edge GEMM + scatter (TE=256) ----------------
// warp w: rw = w>>1 -> rows rw*64..+63; cw = w&1 -> cols cw*64..+63
__device__ __forceinline__ void issue_A256(const __half* __restrict__ Xh,
                                           const int* __restrict__ src,
                                           int ebase, int n, uint32_t abase, int tid) {
#pragma unroll
    for (int j = 0; j < 16; j++) {
        int id = tid + 256 * j;
        int row = id >> 4, c = id & 15;
        const void* g = Xh;
        int sz = 0;
        if (row < n) {
            int e = g_sorted[ebase + row];
            g = (const uint4*)(Xh + (size_t)src[e] * D) + c;
            sz = 16;
        }
        cp16(abase + (uint32_t)row * 256 + swz(row, c) * 16, g, sz);
    }
}

__global__ __launch_bounds__(256, 1)
void k_rgemm_mma(int layer, const int* __restrict__ src, const int* __restrict__ dst) {
    extern __shared__ unsigned char sm[];
    uint32_t sbase = smem_u32(sm);
    int tid = threadIdx.x, w = tid >> 5, lane = tid & 31;
    const int rw = w >> 1, cw = w & 1;

    int r = blockIdx.x / NB;
    int j = blockIdx.x % NB;
    int hist = g_hist[r];
    int sb   = g_base[r];
    int Tr   = (hist + TE - 1) / TE;
    int per  = (Tr + NB - 1) / NB;
    int tb   = j * per;
    int te   = tb + per;
    if (te > Tr) te = Tr;
    int nt = te - tb;
    if (nt <= 0) return;

    // stage W_r once (swizzled)
    const uint4* Wg = (const uint4*)(g_WT[layer] + (size_t)r * D * D);
#pragma unroll
    for (int q = 0; q < 8; q++) {
        int id = tid + 256 * q;
        int row = id >> 4, c = id & 15;
        *(uint4*)(sm + (uint32_t)row * 256 + swz(row, c) * 16) = Wg[id];
    }

    const __half* Xh = layer ? g_Hh : g_Xh;

    // prologue: prefetch tiles tb, tb+1 into bufs 0,1
    {
        int n0 = hist - tb * TE; if (n0 > TE) n0 = TE;
        issue_A256(Xh, src, sb + tb * TE, n0, sbase + SA_BASE, tid);
        cp_commit();
        if (nt > 1) {
            int n1 = hist - (tb + 1) * TE; if (n1 > TE) n1 = TE;
            issue_A256(Xh, src, sb + (tb + 1) * TE, n1, sbase + SA_BASE + ABLK, tid);
        }
        cp_commit();
    }

    const int rsel = ((lane >> 3) & 1) * 8 + (lane & 7);
    const int ks = lane >> 4;
    const int l7 = lane & 7;
    const int g = lane >> 2, tig = lane & 3;
    int buf = 0;

    for (int ti = 0; ti < nt; ti++) {
        int t = tb + ti;
        int ebase = sb + t * TE;
        int n = hist - t * TE; if (n > TE) n = TE;
        uint32_t abase = sbase + SA_BASE + (uint32_t)buf * ABLK;

        asm volatile("cp.async.wait_group 1;" ::: "memory");
        __syncthreads();   // tile ti ready; all warps past mma of ti-1

        // refill buffer consumed at ti-1 with tile ti+2
        if (ti + 2 < nt) {
            int t2 = tb + ti + 2;
            int n2 = hist - t2 * TE; if (n2 > TE) n2 = TE;
            int b2 = buf + 2; if (b2 >= 3) b2 -= 3;
            issue_A256(Xh, src, sb + t2 * TE, n2, sbase + SA_BASE + (uint32_t)b2 * ABLK, tid);
        }
        cp_commit();

        float acc[4][8][4];
#pragma unroll
        for (int a = 0; a < 4; a++)
#pragma unroll
            for (int q = 0; q < 8; q++)
#pragma unroll
                for (int z = 0; z < 4; z++) acc[a][q][z] = 0.f;

        // mainloop: warp = 64 rows x 64 cols
#pragma unroll
        for (int kk = 0; kk < 8; kk++) {
            int c = kk * 2 + ks;
            uint32_t coff = (uint32_t)(((c & 7) ^ l7) | (c & 8)) * 16;
            uint32_t aH[4][4];
#pragma unroll
            for (int a = 0; a < 4; a++) {
                uint32_t ro = (uint32_t)(rw * 64 + a * 16 + rsel) * 256 + coff;
                ldsm4(abase + ro, aH[a][0], aH[a][1], aH[a][2], aH[a][3]);
            }
#pragma unroll
            for (int p = 0; p < 4; p++) {
                uint32_t wo = (uint32_t)(cw * 64 + p * 16 + rsel) * 256 + coff;
                uint32_t bh[4];
                ldsm4(sbase + wo, bh[0], bh[1], bh[2], bh[3]);
#pragma unroll
                for (int a = 0; a < 4; a++) {
                    mma16816(acc[a][2 * p],     aH[a], bh[0], bh[2]);
                    mma16816(acc[a][2 * p + 1], aH[a], bh[1], bh[3]);
                }
            }
        }

        // scatter straight from registers
#pragma unroll
        for (int a = 0; a < 4; a++) {
#pragma unroll
            for (int h = 0; h < 2; h++) {
                int row = rw * 64 + a * 16 + g + h * 8;
                if (row < n) {
                    int e = g_sorted[ebase + row];
                    float* p = g_Z + (size_t)dst[e] * D + cw * 64 + 2 * tig;
#pragma unroll
                    for (int q = 0; q < 8; q++)
                        red_v2(p + q * 8, acc[a][q][2 * h], acc[a][q][2 * h + 1]);
                }
            }
        }

        buf++; if (buf == 3) buf = 0;
    }
}

// ---------------- combine: out = Z/max(cnt,1) + X @ root (+ReLU, +fp16 store) ----------------
// 128-row tiles; warp w: mw = w>>1 -> rows mw*32..+31, nw = w&1 -> cols nw*64..+63
__global__ __launch_bounds__(256, 1)
void k_combine_mma(int layer, float* __restrict__ outp, int use_out) {
    extern __shared__ unsigned char sm[];
    uint32_t sbase = smem_u32(sm);
    int tid = threadIdx.x, w = tid >> 5, lane = tid & 31;
    const int mw = w >> 1, nw = w & 1;
    int t0 = blockIdx.x * 128;

    const uint4* Wg = (const uint4*)g_rootT[layer];
#pragma unroll
    for (int q = 0; q < 8; q++) {
        int id = tid + 256 * q;
        int row = id >> 4, c = id & 15;
        *(uint4*)(sm + (uint32_t)row * 256 + swz(row, c) * 16) = Wg[id];
    }
    const __half* Xh = layer ? g_Hh : g_Xh;
#pragma unroll
    for (int q = 0; q < 8; q++) {
        int id = tid + 256 * q;
        int row = id >> 4, c = id & 15;
        int grow = t0 + row;
        uint4 v = make_uint4(0, 0, 0, 0);
        if (grow < NN) v = ((const uint4*)(Xh + (size_t)grow * D))[c];
        *(uint4*)(sm + WSZ + (uint32_t)row * 256 + swz(row, c) * 16) = v;
    }
    __syncthreads();

    float acc[2][8][4];
#pragma unroll
    for (int a = 0; a < 2; a++)
#pragma unroll
        for (int q = 0; q < 8; q++)
#pragma unroll
            for (int z = 0; z < 4; z++) acc[a][q][z] = 0.f;

    const int rsel = ((lane >> 3) & 1) * 8 + (lane & 7);
    const int ks = lane >> 4;
    const int l7 = lane & 7;
#pragma unroll
    for (int kk = 0; kk < 8; kk++) {
        int c = kk * 2 + ks;
        uint32_t coff = (uint32_t)(((c & 7) ^ l7) | (c & 8)) * 16;
        uint32_t aH[2][4];
#pragma unroll
        for (int a = 0; a < 2; a++) {
            uint32_t ro = (uint32_t)(mw * 32 + a * 16 + rsel) * 256 + coff;
            ldsm4(sbase + WSZ + ro, aH[a][0], aH[a][1], aH[a][2], aH[a][3]);
        }
#pragma unroll
        for (int p = 0; p < 4; p++) {
            uint32_t wo = (uint32_t)(nw * 64 + p * 16 + rsel) * 256 + coff;
            uint32_t bh[4];
            ldsm4(sbase + wo, bh[0], bh[1], bh[2], bh[3]);
#pragma unroll
            for (int a = 0; a < 2; a++) {
                mma16816(acc[a][2 * p],     aH[a], bh[0], bh[2]);
                mma16816(acc[a][2 * p + 1], aH[a], bh[1], bh[3]);
            }
        }
    }

    const int g = lane >> 2, tig = lane & 3;
#pragma unroll
    for (int a = 0; a < 2; a++) {
#pragma unroll
        for (int h = 0; h < 2; h++) {
            int grow = t0 + mw * 32 + a * 16 + g + h * 8;
            if (grow < NN) {
                int cc = g_cnt[grow];
                float ic = 1.0f / (float)(cc > 1 ? cc : 1);
#pragma unroll
                for (int q = 0; q < 8; q++) {
                    int col = nw * 64 + q * 8 + 2 * tig;
                    float2 z = *(const float2*)(g_Z + (size_t)grow * D + col);
                    float o0 = acc[a][q][2 * h]     + z.x * ic;
                    float o1 = acc[a][q][2 * h + 1] + z.y * ic;
                    if (use_out) {
                        *(float2*)(outp + (size_t)grow * D + col) = make_float2(o0, o1);
                    } else {
                        o0 = o0 > 0.f ? o0 : 0.f;
                        o1 = o1 > 0.f ? o1 : 0.f;
                        __half hh[2] = {__float2half_rn(o0), __float2half_rn(o1)};
                        *(uint32_t*)(g_Hh + (size_t)grow * D + col) = *(uint32_t*)hh;
                    }
                }
            }
        }
    }
}

// ---------------- host ----------------
extern "C" void kernel_launch(void* const* d_in, const int* in_sizes, int n_in,
                              void* d_out, int out_size) {
    const int*   entity = (const int*)d_in[0];
    const int*   eidx   = (const int*)d_in[1];
    const int*   etype  = (const int*)d_in[2];
    const float* emb    = (const float*)d_in[4];
    const float* W1     = (const float*)d_in[5];
    const float* root1  = (const float*)d_in[6];
    const float* W2     = (const float*)d_in[7];
    const float* root2  = (const float*)d_in[8];
    const int* src = eidx;
    const int* dst = eidx + NE;
    float* out = (float*)d_out;

    static int attr_done = 0;
    if (!attr_done) {
        cudaFuncSetAttribute(k_rgemm_mma,   cudaFuncAttributeMaxDynamicSharedMemorySize, SMEM_RG);
        cudaFuncSetAttribute(k_combine_mma, cudaFuncAttributeMaxDynamicSharedMemorySize, SMEM_CB);
        attr_done = 1;
    }

    int gE = (NE + 255) / 256;
    int gN = (NN + 255) / 256;
    int gZ = (NN * D / 4) / 256;
    int gC = (NN + 127) / 128;

    k_zero_meta<<<gN, 256>>>();
    k_hist<<<gE, 256>>>(etype, dst);
    k_scan<<<1, 1>>>();
    k_sort<<<gE, 256>>>(etype);
    k_prepW<<<34, 256>>>(W1, W2, root1, root2);
    k_gather<<<NN / 8, 256>>>(entity, emb);

    // Layer 1
    k_zeroZ<<<gZ, 256>>>();
    k_rgemm_mma<<<R * NB, 256, SMEM_RG>>>(0, src, dst);
    k_combine_mma<<<gC, 256, SMEM_CB>>>(0, out, 0);

    // Layer 2
    k_zeroZ<<<gZ, 256>>>();
    k_rgemm_mma<<<R * NB, 256, SMEM_RG>>>(1, src, dst);
    k_combine_mma<<<gC, 256, SMEM_CB>>>(1, out, 1);
}

// round 12
// speedup vs baseline: 1.4115x; 1.0157x over previous
#include <cuda_runtime.h>
#include <cuda_fp16.h>
#include <cstdint>

#define NN 100000
#define NE 1000000
#define D  128
#define R  16
#define TE 256   // edges per MMA tile
#define NB 9     // blocks per relation (grid = R*NB = 144)

// ---------------- device scratch (no allocation allowed) ----------------
__device__ float g_Z[(size_t)NN * D];
__device__ __half g_Xh[(size_t)NN * D];          // layer-1 input, fp16
__device__ __half g_Hh[(size_t)NN * D];          // layer-1 output, fp16
__device__ __half g_WT[2][R * D * D];            // [layer][r][n][k] = W[k][n], fp16
__device__ __half g_rootT[2][D * D];
__device__ int g_cnt[NN];
__device__ int g_sorted[NE];
__device__ int g_hist[R];
__device__ int g_base[R + 1];
__device__ int g_cursor[R];

// ---- smem maps: pitch 256B, XOR chunk swizzle (conflict-free ldsm) ----
#define WSZ     32768
#define ABLK    65536
#define SA_BASE 32768
#define SMEM_RG 229376           // 32768 + 3*65536
#define SMEM_CB 65536

// chunk swizzle: logical 16B chunk c (0..15) of row -> physical chunk
__device__ __forceinline__ uint32_t swz(int row, int c) {
    return (uint32_t)(((c & 7) ^ (row & 7)) | (c & 8));
}

// ---------------- helpers ----------------
__device__ __forceinline__ uint32_t smem_u32(const void* p) {
    uint32_t a;
    asm("{ .reg .u64 t; cvta.to.shared.u64 t, %1; cvt.u32.u64 %0, t; }" : "=r"(a) : "l"(p));
    return a;
}
__device__ __forceinline__ void red_v4(float* p, float a, float b, float c, float d) {
    asm volatile("red.global.add.v4.f32 [%0], {%1,%2,%3,%4};" ::
                 "l"(p), "f"(a), "f"(b), "f"(c), "f"(d) : "memory");
}
__device__ __forceinline__ void ldsm4(uint32_t addr, uint32_t& r0, uint32_t& r1,
                                      uint32_t& r2, uint32_t& r3) {
    asm volatile("ldmatrix.sync.aligned.m8n8.x4.shared.b16 {%0,%1,%2,%3}, [%4];"
                 : "=r"(r0), "=r"(r1), "=r"(r2), "=r"(r3) : "r"(addr));
}
__device__ __forceinline__ void mma16816(float* d, const uint32_t* a, uint32_t b0, uint32_t b1) {
    asm volatile(
        "mma.sync.aligned.m16n8k16.row.col.f32.f16.f16.f32 "
        "{%0,%1,%2,%3}, {%4,%5,%6,%7}, {%8,%9}, {%0,%1,%2,%3};"
        : "+f"(d[0]), "+f"(d[1]), "+f"(d[2]), "+f"(d[3])
        : "r"(a[0]), "r"(a[1]), "r"(a[2]), "r"(a[3]), "r"(b0), "r"(b1));
}
__device__ __forceinline__ void cp16(uint32_t saddr, const void* gaddr, int sz) {
    asm volatile("cp.async.cg.shared.global [%0], [%1], 16, %2;"
                 :: "r"(saddr), "l"(gaddr), "r"(sz) : "memory");
}
__device__ __forceinline__ void cp_commit() { asm volatile("cp.async.commit_group;" ::: "memory"); }

// ---------------- setup kernels ----------------
__global__ void k_zero_meta() {
    int i = blockIdx.x * blockDim.x + threadIdx.x;
    if (i < R)  g_hist[i] = 0;
    if (i < NN) g_cnt[i] = 0;
}

__global__ void k_hist(const int* __restrict__ et, const int* __restrict__ dst) {
    __shared__ int sh[R];
    if (threadIdx.x < R) sh[threadIdx.x] = 0;
    __syncthreads();
    int e = blockIdx.x * blockDim.x + threadIdx.x;
    if (e < NE) {
        atomicAdd(&sh[et[e]], 1);
        atomicAdd(&g_cnt[dst[e]], 1);
    }
    __syncthreads();
    if (threadIdx.x < R && sh[threadIdx.x]) atomicAdd(&g_hist[threadIdx.x], sh[threadIdx.x]);
}

__global__ void k_scan() {
    int acc = 0;
    for (int r = 0; r < R; r++) {
        g_base[r] = acc;
        g_cursor[r] = acc;
        acc += g_hist[r];
    }
    g_base[R] = acc;
}

__global__ void k_sort(const int* __restrict__ et) {
    __shared__ int lh[R], lb[R];
    if (threadIdx.x < R) lh[threadIdx.x] = 0;
    __syncthreads();
    int e = blockIdx.x * blockDim.x + threadIdx.x;
    int t = -1, lp = 0;
    if (e < NE) {
        t = et[e];
        lp = atomicAdd(&lh[t], 1);
    }
    __syncthreads();
    if (threadIdx.x < R && lh[threadIdx.x] > 0)
        lb[threadIdx.x] = atomicAdd(&g_cursor[threadIdx.x], lh[threadIdx.x]);
    __syncthreads();
    if (t >= 0) g_sorted[lb[t] + lp] = e;
}

// transpose + fp16: W[k][n] -> WT[n][k]; bx 0..31 relations, 32..33 roots
__global__ void k_prepW(const float* __restrict__ W1, const float* __restrict__ W2,
                        const float* __restrict__ root1, const float* __restrict__ root2) {
    int bx = blockIdx.x;
    const float* W;
    __half* hi;
    if (bx < 32) {
        int layer = bx >> 4, r = bx & 15;
        W  = (layer ? W2 : W1) + (size_t)r * D * D;
        hi = g_WT[layer] + (size_t)r * D * D;
    } else {
        int layer = bx - 32;
        W  = layer ? root2 : root1;
        hi = g_rootT[layer];
    }
    for (int idx = threadIdx.x; idx < D * D; idx += blockDim.x) {
        int n = idx >> 7, k = idx & 127;
        hi[idx] = __float2half_rn(W[k * D + n]);
    }
}

__global__ void k_gather(const int* __restrict__ ent, const float* __restrict__ emb) {
    int id = blockIdx.x * blockDim.x + threadIdx.x;
    int n = id >> 5, t = id & 31;
    float4 v = ((const float4*)(emb + (size_t)ent[n] * D))[t];
    __half h[4] = {__float2half_rn(v.x), __float2half_rn(v.y),
                   __float2half_rn(v.z), __float2half_rn(v.w)};
    *(uint2*)(g_Xh + (size_t)n * D + t * 4) = *(uint2*)h;
}

__global__ void k_zeroZ() {
    size_t i = (size_t)blockIdx.x * blockDim.x + threadIdx.x;
    ((float4*)g_Z)[i] = make_float4(0.f, 0.f, 0.f, 0.f);
}

// ---------------- persistent edge GEMM + scatter (TE=256) ----------------
__device__ __forceinline__ void issue_A256(const __half* __restrict__ Xh,
                                           const int* __restrict__ src,
                                           int ebase, int n, uint32_t abase, int tid) {
#pragma unroll
    for (int j = 0; j < 16; j++) {
        int id = tid + 256 * j;
        int row = id >> 4, c = id & 15;
        const void* g = Xh;
        int sz = 0;
        if (row < n) {
            int e = g_sorted[ebase + row];
            g = (const uint4*)(Xh + (size_t)src[e] * D) + c;
            sz = 16;
        }
        cp16(abase + (uint32_t)row * 256 + swz(row, c) * 16, g, sz);
    }
}

__global__ __launch_bounds__(256, 1)
void k_rgemm_mma(int layer, const int* __restrict__ src, const int* __restrict__ dst) {
    extern __shared__ unsigned char sm[];
    uint32_t sbase = smem_u32(sm);
    int tid = threadIdx.x, w = tid >> 5, lane = tid & 31;
    const int rw = w >> 1, cw = w & 1;

    int r = blockIdx.x / NB;
    int j = blockIdx.x % NB;
    int hist = g_hist[r];
    int sb   = g_base[r];
    int Tr   = (hist + TE - 1) / TE;
    int per  = (Tr + NB - 1) / NB;
    int tb   = j * per;
    int te   = tb + per;
    if (te > Tr) te = Tr;
    int nt = te - tb;
    if (nt <= 0) return;

    // stage W_r once (swizzled)
    const uint4* Wg = (const uint4*)(g_WT[layer] + (size_t)r * D * D);
#pragma unroll
    for (int q = 0; q < 8; q++) {
        int id = tid + 256 * q;
        int row = id >> 4, c = id & 15;
        *(uint4*)(sm + (uint32_t)row * 256 + swz(row, c) * 16) = Wg[id];
    }

    const __half* Xh = layer ? g_Hh : g_Xh;

    // prologue: prefetch tiles tb, tb+1 into bufs 0,1
    {
        int n0 = hist - tb * TE; if (n0 > TE) n0 = TE;
        issue_A256(Xh, src, sb + tb * TE, n0, sbase + SA_BASE, tid);
        cp_commit();
        if (nt > 1) {
            int n1 = hist - (tb + 1) * TE; if (n1 > TE) n1 = TE;
            issue_A256(Xh, src, sb + (tb + 1) * TE, n1, sbase + SA_BASE + ABLK, tid);
        }
        cp_commit();
    }

    const int rsel = ((lane >> 3) & 1) * 8 + (lane & 7);
    const int ks = lane >> 4;
    const int l7 = lane & 7;
    const int g = lane >> 2, tig = lane & 3;
    const int t4 = (tig >> 1) * 4;            // col base within 8 for the lane pair
    const bool lowlane = (tig & 1) == 0;
    int buf = 0;

    for (int ti = 0; ti < nt; ti++) {
        int t = tb + ti;
        int ebase = sb + t * TE;
        int n = hist - t * TE; if (n > TE) n = TE;
        uint32_t abase = sbase + SA_BASE + (uint32_t)buf * ABLK;

        asm volatile("cp.async.wait_group 1;" ::: "memory");
        __syncthreads();   // tile ti ready; all warps past mma of ti-1

        // refill buffer consumed at ti-1 with tile ti+2
        if (ti + 2 < nt) {
            int t2 = tb + ti + 2;
            int n2 = hist - t2 * TE; if (n2 > TE) n2 = TE;
            int b2 = buf + 2; if (b2 >= 3) b2 -= 3;
            issue_A256(Xh, src, sb + t2 * TE, n2, sbase + SA_BASE + (uint32_t)b2 * ABLK, tid);
        }
        cp_commit();

        float acc[4][8][4];
#pragma unroll
        for (int a = 0; a < 4; a++)
#pragma unroll
            for (int q = 0; q < 8; q++)
#pragma unroll
                for (int z = 0; z < 4; z++) acc[a][q][z] = 0.f;

        // mainloop: warp = 64 rows x 64 cols
#pragma unroll
        for (int kk = 0; kk < 8; kk++) {
            int c = kk * 2 + ks;
            uint32_t coff = (uint32_t)(((c & 7) ^ l7) | (c & 8)) * 16;
            uint32_t aH[4][4];
#pragma unroll
            for (int a = 0; a < 4; a++) {
                uint32_t ro = (uint32_t)(rw * 64 + a * 16 + rsel) * 256 + coff;
                ldsm4(abase + ro, aH[a][0], aH[a][1], aH[a][2], aH[a][3]);
            }
#pragma unroll
            for (int p = 0; p < 4; p++) {
                uint32_t wo = (uint32_t)(cw * 64 + p * 16 + rsel) * 256 + coff;
                uint32_t bh[4];
                ldsm4(sbase + wo, bh[0], bh[1], bh[2], bh[3]);
#pragma unroll
                for (int a = 0; a < 4; a++) {
                    mma16816(acc[a][2 * p],     aH[a], bh[0], bh[2]);
                    mma16816(acc[a][2 * p + 1], aH[a], bh[1], bh[3]);
                }
            }
        }

        // shuffle-paired float4 scatter: lanes L and L^1 share a row; one
        // shfl pair converts two red.v2 into one red.v4 per q.
#pragma unroll
        for (int a = 0; a < 4; a++) {
#pragma unroll
            for (int h = 0; h < 2; h++) {
                int row = rw * 64 + a * 16 + g + h * 8;
                bool act = row < n;
                float* p = nullptr;
                if (act) {
                    int e = g_sorted[ebase + row];
                    p = g_Z + (size_t)dst[e] * D + cw * 64 + t4;
                }
#pragma unroll
                for (int m = 0; m < 4; m++) {
                    int q0 = 2 * m, q1 = 2 * m + 1;
                    float v0 = lowlane ? acc[a][q1][2 * h]     : acc[a][q0][2 * h];
                    float v1 = lowlane ? acc[a][q1][2 * h + 1] : acc[a][q0][2 * h + 1];
                    float s0 = __shfl_xor_sync(0xffffffffu, v0, 1);
                    float s1 = __shfl_xor_sync(0xffffffffu, v1, 1);
                    if (act) {
                        if (lowlane)
                            red_v4(p + q0 * 8, acc[a][q0][2 * h], acc[a][q0][2 * h + 1], s0, s1);
                        else
                            red_v4(p + q1 * 8, s0, s1, acc[a][q1][2 * h], acc[a][q1][2 * h + 1]);
                    }
                }
            }
        }

        buf++; if (buf == 3) buf = 0;
    }
}

// ---------------- combine: out = Z/max(cnt,1) + X @ root (+ReLU, +fp16 store) ----------------
__global__ __launch_bounds__(256, 1)
void k_combine_mma(int layer, float* __restrict__ outp, int use_out) {
    extern __shared__ unsigned char sm[];
    uint32_t sbase = smem_u32(sm);
    int tid = threadIdx.x, w = tid >> 5, lane = tid & 31;
    const int mw = w >> 1, nw = w & 1;
    int t0 = blockIdx.x * 128;

    const uint4* Wg = (const uint4*)g_rootT[layer];
#pragma unroll
    for (int q = 0; q < 8; q++) {
        int id = tid + 256 * q;
        int row = id >> 4, c = id & 15;
        *(uint4*)(sm + (uint32_t)row * 256 + swz(row, c) * 16) = Wg[id];
    }
    const __half* Xh = layer ? g_Hh : g_Xh;
#pragma unroll
    for (int q = 0; q < 8; q++) {
        int id = tid + 256 * q;
        int row = id >> 4, c = id & 15;
        int grow = t0 + row;
        uint4 v = make_uint4(0, 0, 0, 0);
        if (grow < NN) v = ((const uint4*)(Xh + (size_t)grow * D))[c];
        *(uint4*)(sm + WSZ + (uint32_t)row * 256 + swz(row, c) * 16) = v;
    }
    __syncthreads();

    float acc[2][8][4];
#pragma unroll
    for (int a = 0; a < 2; a++)
#pragma unroll
        for (int q = 0; q < 8; q++)
#pragma unroll
            for (int z = 0; z < 4; z++) acc[a][q][z] = 0.f;

    const int rsel = ((lane >> 3) & 1) * 8 + (lane & 7);
    const int ks = lane >> 4;
    const int l7 = lane & 7;
#pragma unroll
    for (int kk = 0; kk < 8; kk++) {
        int c = kk * 2 + ks;
        uint32_t coff = (uint32_t)(((c & 7) ^ l7) | (c & 8)) * 16;
        uint32_t aH[2][4];
#pragma unroll
        for (int a = 0; a < 2; a++) {
            uint32_t ro = (uint32_t)(mw * 32 + a * 16 + rsel) * 256 + coff;
            ldsm4(sbase + WSZ + ro, aH[a][0], aH[a][1], aH[a][2], aH[a][3]);
        }
#pragma unroll
        for (int p = 0; p < 4; p++) {
            uint32_t wo = (uint32_t)(nw * 64 + p * 16 + rsel) * 256 + coff;
            uint32_t bh[4];
            ldsm4(sbase + wo, bh[0], bh[1], bh[2], bh[3]);
#pragma unroll
            for (int a = 0; a < 2; a++) {
                mma16816(acc[a][2 * p],     aH[a], bh[0], bh[2]);
                mma16816(acc[a][2 * p + 1], aH[a], bh[1], bh[3]);
            }
        }
    }

    const int g = lane >> 2, tig = lane & 3;
#pragma unroll
    for (int a = 0; a < 2; a++) {
#pragma unroll
        for (int h = 0; h < 2; h++) {
            int grow = t0 + mw * 32 + a * 16 + g + h * 8;
            if (grow < NN) {
                int cc = g_cnt[grow];
                float ic = 1.0f / (float)(cc > 1 ? cc : 1);
#pragma unroll
                for (int q = 0; q < 8; q++) {
                    int col = nw * 64 + q * 8 + 2 * tig;
                    float2 z = *(const float2*)(g_Z + (size_t)grow * D + col);
                    float o0 = acc[a][q][2 * h]     + z.x * ic;
                    float o1 = acc[a][q][2 * h + 1] + z.y * ic;
                    if (use_out) {
                        *(float2*)(outp + (size_t)grow * D + col) = make_float2(o0, o1);
                    } else {
                        o0 = o0 > 0.f ? o0 : 0.f;
                        o1 = o1 > 0.f ? o1 : 0.f;
                        __half hh[2] = {__float2half_rn(o0), __float2half_rn(o1)};
                        *(uint32_t*)(g_Hh + (size_t)grow * D + col) = *(uint32_t*)hh;
                    }
                }
            }
        }
    }
}

// ---------------- host ----------------
extern "C" void kernel_launch(void* const* d_in, const int* in_sizes, int n_in,
                              void* d_out, int out_size) {
    const int*   entity = (const int*)d_in[0];
    const int*   eidx   = (const int*)d_in[1];
    const int*   etype  = (const int*)d_in[2];
    const float* emb    = (const float*)d_in[4];
    const float* W1     = (const float*)d_in[5];
    const float* root1  = (const float*)d_in[6];
    const float* W2     = (const float*)d_in[7];
    const float* root2  = (const float*)d_in[8];
    const int* src = eidx;
    const int* dst = eidx + NE;
    float* out = (float*)d_out;

    static int attr_done = 0;
    if (!attr_done) {
        cudaFuncSetAttribute(k_rgemm_mma,   cudaFuncAttributeMaxDynamicSharedMemorySize, SMEM_RG);
        cudaFuncSetAttribute(k_combine_mma, cudaFuncAttributeMaxDynamicSharedMemorySize, SMEM_CB);
        attr_done = 1;
    }

    int gE = (NE + 255) / 256;
    int gN = (NN + 255) / 256;
    int gZ = (NN * D / 4) / 256;
    int gC = (NN + 127) / 128;

    k_zero_meta<<<gN, 256>>>();
    k_hist<<<gE, 256>>>(etype, dst);
    k_scan<<<1, 1>>>();
    k_sort<<<gE, 256>>>(etype);
    k_prepW<<<34, 256>>>(W1, W2, root1, root2);
    k_gather<<<NN / 8, 256>>>(entity, emb);

    // Layer 1
    k_zeroZ<<<gZ, 256>>>();
    k_rgemm_mma<<<R * NB, 256, SMEM_RG>>>(0, src, dst);
    k_combine_mma<<<gC, 256, SMEM_CB>>>(0, out, 0);

    // Layer 2
    k_zeroZ<<<gZ, 256>>>();
    k_rgemm_mma<<<R * NB, 256, SMEM_RG>>>(1, src, dst);
    k_combine_mma<<<gC, 256, SMEM_CB>>>(1, out, 1);
}